// round 14
// baseline (speedup 1.0000x reference)
#include <cuda_runtime.h>
#include <cuda_fp16.h>
#include <cstdint>

#define NN 50000
#define EE 800000
#define IN_CH 256
#define HEADS 4
#define OUT_CH 32
#define HC 128
#define NEG_SLOPE 0.2f
#define EPSV 1e-16f

#define SCAN_T 1024
#define NB1 ((NN + SCAN_T - 1) / SCAN_T)

#define BM 128
#define BN 128
#define BK 32
#define APAD 4
#define BPAD 8

#define NGEMMB ((NN + BM - 1) / BM)          // 391
#define NDEGB  ((EE + 255) / 256)            // 3125

// ---------------- scratch ----------------
__device__ __half g_hh[(size_t)NN * HC];         // projected features, fp16
__device__ float g_bk[IN_CH * HC];               // W as [k][n], tf32-rounded
__device__ float g_asrc[NN * HEADS];
__device__ float g_adst[NN * HEADS];
__device__ int   g_deg[NN];
__device__ int   g_offsets[NN + 1];
__device__ int   g_cursor[NN];
__device__ int   g_blocksums[NB1];
__device__ int   g_csr_src[EE];

__device__ __forceinline__ float tf32r(float x) {
    uint32_t b;
    asm("cvt.rna.tf32.f32 %0, %1;" : "=r"(b) : "f"(x));
    return __uint_as_float(b);
}

// ---------------- 0: prep = zero degrees + W -> [k][n] tf32 table ----------------
__global__ void prep_kernel(const float* __restrict__ w) {
    int idx = blockIdx.x * blockDim.x + threadIdx.x;
    if (idx < NN) g_deg[idx] = 0;
    if (idx < IN_CH * HC) {
        int k = idx >> 7, n = idx & 127;
        g_bk[idx] = tf32r(w[(n >> 5) * (IN_CH * OUT_CH) + k * OUT_CH + (n & 31)]);
    }
}

// ---------------- 1: GEMM + fused attdot + fp16 h store, trailing deg blocks ----------------
__global__ __launch_bounds__(256, 2) void gemm_mma_kernel(const float* __restrict__ x,
                                                          const float* __restrict__ att,
                                                          const int* __restrict__ ei) {
    if (blockIdx.x >= NGEMMB) {
        int e = (blockIdx.x - NGEMMB) * 256 + threadIdx.x;
        if (e < EE) atomicAdd(&g_deg[ei[EE + e]], 1);
        return;
    }

    __shared__ float As[BM][BK + APAD];
    __shared__ float Bs[BK][BN + BPAD];
    __shared__ float s_a1[HEADS][OUT_CH];
    __shared__ float s_a2[HEADS][OUT_CH];
    const int tid = threadIdx.x;
    const int lane = tid & 31;
    const int wid = tid >> 5;
    const int wm = wid >> 1;
    const int wn = wid & 1;
    const int block_m = blockIdx.x * BM;
    const int g = lane >> 2;
    const int tg = lane & 3;

    if (tid < HEADS * OUT_CH) {
        int hh = tid >> 5, cc = tid & 31;
        s_a1[hh][cc] = att[hh * (2 * OUT_CH) + cc];
        s_a2[hh][cc] = att[hh * (2 * OUT_CH) + OUT_CH + cc];
    }

    float c[2][8][4];
#pragma unroll
    for (int mt = 0; mt < 2; mt++)
#pragma unroll
        for (int nt = 0; nt < 8; nt++)
#pragma unroll
            for (int j = 0; j < 4; j++) c[mt][nt][j] = 0.f;

    {
#pragma unroll
        for (int i = 0; i < 4; i++) {
            int idx = tid + i * 256;
            int r = idx >> 3, c4 = idx & 7;
            int gm = block_m + r;
            float4 v = make_float4(0.f, 0.f, 0.f, 0.f);
            if (gm < NN) v = *(const float4*)(x + (size_t)gm * IN_CH + c4 * 4);
            v.x = tf32r(v.x); v.y = tf32r(v.y); v.z = tf32r(v.z); v.w = tf32r(v.w);
            *(float4*)&As[r][c4 * 4] = v;
        }
#pragma unroll
        for (int i = 0; i < 4; i++) {
            int idx = tid + i * 256;
            int r = idx >> 5, c4 = idx & 31;
            *(float4*)&Bs[r][c4 * 4] = *(const float4*)(g_bk + r * HC + c4 * 4);
        }
    }
    __syncthreads();

    for (int k0 = 0; k0 < IN_CH; k0 += BK) {
        const bool has_next = (k0 + BK) < IN_CH;
        float4 pa[4], pb[4];
        if (has_next) {
#pragma unroll
            for (int i = 0; i < 4; i++) {
                int idx = tid + i * 256;
                int r = idx >> 3, c4 = idx & 7;
                int gm = block_m + r;
                pa[i] = make_float4(0.f, 0.f, 0.f, 0.f);
                if (gm < NN) pa[i] = *(const float4*)(x + (size_t)gm * IN_CH + k0 + BK + c4 * 4);
            }
#pragma unroll
            for (int i = 0; i < 4; i++) {
                int idx = tid + i * 256;
                int r = idx >> 5, c4 = idx & 31;
                pb[i] = *(const float4*)(g_bk + (k0 + BK + r) * HC + c4 * 4);
            }
        }

#pragma unroll
        for (int kk = 0; kk < BK; kk += 8) {
            uint32_t a[2][4];
#pragma unroll
            for (int mt = 0; mt < 2; mt++) {
                int ar = wm * 32 + mt * 16 + g;
                a[mt][0] = __float_as_uint(As[ar][kk + tg]);
                a[mt][1] = __float_as_uint(As[ar + 8][kk + tg]);
                a[mt][2] = __float_as_uint(As[ar][kk + tg + 4]);
                a[mt][3] = __float_as_uint(As[ar + 8][kk + tg + 4]);
            }
#pragma unroll
            for (int nt = 0; nt < 8; nt++) {
                int bc = wn * 64 + nt * 8 + g;
                uint32_t b0 = __float_as_uint(Bs[kk + tg][bc]);
                uint32_t b1 = __float_as_uint(Bs[kk + tg + 4][bc]);
#pragma unroll
                for (int mt = 0; mt < 2; mt++) {
                    asm volatile(
                        "mma.sync.aligned.m16n8k8.row.col.f32.tf32.tf32.f32 "
                        "{%0,%1,%2,%3}, {%4,%5,%6,%7}, {%8,%9}, {%0,%1,%2,%3};"
                        : "+f"(c[mt][nt][0]), "+f"(c[mt][nt][1]),
                          "+f"(c[mt][nt][2]), "+f"(c[mt][nt][3])
                        : "r"(a[mt][0]), "r"(a[mt][1]), "r"(a[mt][2]), "r"(a[mt][3]),
                          "r"(b0), "r"(b1));
                }
            }
        }
        __syncthreads();
        if (has_next) {
#pragma unroll
            for (int i = 0; i < 4; i++) {
                int idx = tid + i * 256;
                int r = idx >> 3, c4 = idx & 7;
                float4 v = pa[i];
                v.x = tf32r(v.x); v.y = tf32r(v.y); v.z = tf32r(v.z); v.w = tf32r(v.w);
                *(float4*)&As[r][c4 * 4] = v;
            }
#pragma unroll
            for (int i = 0; i < 4; i++) {
                int idx = tid + i * 256;
                int r = idx >> 5, c4 = idx & 31;
                *(float4*)&Bs[r][c4 * 4] = pb[i];
            }
            __syncthreads();
        }
    }

    // ---- epilogue: fp16 h store + fused attention dots ----
    float ps[2][2][2], pd[2][2][2];
#pragma unroll
    for (int mt = 0; mt < 2; mt++)
#pragma unroll
        for (int rh = 0; rh < 2; rh++)
#pragma unroll
            for (int hl = 0; hl < 2; hl++) { ps[mt][rh][hl] = 0.f; pd[mt][rh][hl] = 0.f; }

#pragma unroll
    for (int mt = 0; mt < 2; mt++) {
#pragma unroll
        for (int nt = 0; nt < 8; nt++) {
            const int col = wn * 64 + nt * 8 + tg * 2;
            const int hl = nt >> 2;
            const int head = 2 * wn + hl;
            const int colh = (nt & 3) * 8 + tg * 2;
            const float a10 = s_a1[head][colh], a11 = s_a1[head][colh + 1];
            const float a20 = s_a2[head][colh], a21 = s_a2[head][colh + 1];
            const int r0 = block_m + wm * 32 + mt * 16 + g;
            const int r1 = r0 + 8;
            if (r0 < NN)
                *(__half2*)(g_hh + (size_t)r0 * HC + col) =
                    __floats2half2_rn(c[mt][nt][0], c[mt][nt][1]);
            if (r1 < NN)
                *(__half2*)(g_hh + (size_t)r1 * HC + col) =
                    __floats2half2_rn(c[mt][nt][2], c[mt][nt][3]);
            ps[mt][0][hl] += c[mt][nt][0] * a10 + c[mt][nt][1] * a11;
            ps[mt][1][hl] += c[mt][nt][2] * a10 + c[mt][nt][3] * a11;
            pd[mt][0][hl] += c[mt][nt][0] * a20 + c[mt][nt][1] * a21;
            pd[mt][1][hl] += c[mt][nt][2] * a20 + c[mt][nt][3] * a21;
        }
    }
#pragma unroll
    for (int off = 1; off <= 2; off <<= 1) {
#pragma unroll
        for (int mt = 0; mt < 2; mt++)
#pragma unroll
            for (int rh = 0; rh < 2; rh++)
#pragma unroll
                for (int hl = 0; hl < 2; hl++) {
                    ps[mt][rh][hl] += __shfl_xor_sync(0xFFFFFFFF, ps[mt][rh][hl], off);
                    pd[mt][rh][hl] += __shfl_xor_sync(0xFFFFFFFF, pd[mt][rh][hl], off);
                }
    }
    if (tg == 0) {
#pragma unroll
        for (int mt = 0; mt < 2; mt++)
#pragma unroll
            for (int rh = 0; rh < 2; rh++) {
                int row = block_m + wm * 32 + mt * 16 + g + rh * 8;
                if (row < NN) {
#pragma unroll
                    for (int hl = 0; hl < 2; hl++) {
                        g_asrc[row * 4 + 2 * wn + hl] = ps[mt][rh][hl];
                        g_adst[row * 4 + 2 * wn + hl] = pd[mt][rh][hl];
                    }
                }
            }
    }
}

// ---------------- 4a: scan degrees within tiles ----------------
__global__ void scan1_kernel() {
    __shared__ int sm[SCAN_T];
    int b = blockIdx.x, t = threadIdx.x;
    int i = b * SCAN_T + t;
    int v = (i < NN) ? g_deg[i] : 0;
    sm[t] = v;
    __syncthreads();
    for (int off = 1; off < SCAN_T; off <<= 1) {
        int add = (t >= off) ? sm[t - off] : 0;
        __syncthreads();
        sm[t] += add;
        __syncthreads();
    }
    if (i < NN) g_offsets[i] = sm[t] - v;
    if (t == SCAN_T - 1) g_blocksums[b] = sm[t];
}

// ---------------- 4b: add tile prefix (computed in-block) + init cursor ----------------
__global__ void scan3_kernel() {
    __shared__ int s_pref;
    int t = threadIdx.x;
    int base = blockIdx.x * 256;
    int tile = base >> 10;  // all 256 nodes of this block share one tile
    if (t < 32) {
        int acc = 0;
        for (int j = t; j < tile; j += 32) acc += g_blocksums[j];
#pragma unroll
        for (int off = 16; off > 0; off >>= 1)
            acc += __shfl_xor_sync(0xFFFFFFFF, acc, off);
        if (t == 0) s_pref = acc;
    }
    __syncthreads();
    int i = base + t;
    if (i < NN) {
        int o = g_offsets[i] + s_pref;
        g_offsets[i] = o;
        g_cursor[i] = o;
    }
    if (i == 0) g_offsets[NN] = EE;
}

// ---------------- 5: CSR permutation fill (src only) ----------------
__global__ void edgefill_kernel(const int* __restrict__ ei) {
    int e = blockIdx.x * blockDim.x + threadIdx.x;
    if (e >= EE) return;
    int src = ei[e];
    int dst = ei[EE + e];
    int pos = atomicAdd(&g_cursor[dst], 1);
    g_csr_src[pos] = src;
}

// ---------------- 6: gather-aggregate, on-the-fly softmax weights ----------------
__global__ __launch_bounds__(128) void aggregate_kernel(float* __restrict__ out,
                                                        const float* __restrict__ bias) {
    int n = blockIdx.x;
    int t = threadIdx.x;
    int head = t >> 5;
    int beg = g_offsets[n];
    int end = g_offsets[n + 1];
    const float adv = g_adst[n * 4 + head];  // uniform per (block, warp)
    const __half* hb = g_hh + t;
    float acc = 0.f, sw = 0.f;
    int i = beg;
    for (; i + 3 < end; i += 4) {
        int s0 = g_csr_src[i];
        int s1 = g_csr_src[i + 1];
        int s2 = g_csr_src[i + 2];
        int s3 = g_csr_src[i + 3];
        float a0 = g_asrc[s0 * 4 + head] + adv;
        float a1 = g_asrc[s1 * 4 + head] + adv;
        float a2 = g_asrc[s2 * 4 + head] + adv;
        float a3 = g_asrc[s3 * 4 + head] + adv;
        a0 = a0 > 0.f ? a0 : NEG_SLOPE * a0;
        a1 = a1 > 0.f ? a1 : NEG_SLOPE * a1;
        a2 = a2 > 0.f ? a2 : NEG_SLOPE * a2;
        a3 = a3 > 0.f ? a3 : NEG_SLOPE * a3;
        float w0 = __expf(a0);
        float w1 = __expf(a1);
        float w2 = __expf(a2);
        float w3 = __expf(a3);
        float v0 = __half2float(hb[(size_t)s0 * HC]);
        float v1 = __half2float(hb[(size_t)s1 * HC]);
        float v2 = __half2float(hb[(size_t)s2 * HC]);
        float v3 = __half2float(hb[(size_t)s3 * HC]);
        acc += v0 * w0 + v1 * w1 + v2 * w2 + v3 * w3;
        sw += w0 + w1 + w2 + w3;
    }
    for (; i < end; i++) {
        int s0 = g_csr_src[i];
        float a0 = g_asrc[s0 * 4 + head] + adv;
        a0 = a0 > 0.f ? a0 : NEG_SLOPE * a0;
        float w0 = __expf(a0);
        acc += __half2float(hb[(size_t)s0 * HC]) * w0;
        sw += w0;
    }
    out[(size_t)n * HC + t] = acc / (sw + EPSV) + __ldg(bias + t);
}

// ---------------- launcher ----------------
extern "C" void kernel_launch(void* const* d_in, const int* in_sizes, int n_in,
                              void* d_out, int out_size) {
    const float* x    = (const float*)d_in[0];
    const int* ei     = (const int*)d_in[1];
    const float* w    = (const float*)d_in[2];
    const float* att  = (const float*)d_in[3];
    const float* bias = (const float*)d_in[4];
    float* out = (float*)d_out;

    prep_kernel<<<(NN + 255) / 256, 256>>>(w);
    gemm_mma_kernel<<<NGEMMB + NDEGB, 256>>>(x, att, ei);
    scan1_kernel<<<NB1, SCAN_T>>>();
    scan3_kernel<<<(NN + 255) / 256, 256>>>();
    edgefill_kernel<<<(EE + 255) / 256, 256>>>(ei);
    aggregate_kernel<<<NN, 128>>>(out, bias);
}

// round 16
// speedup vs baseline: 1.1089x; 1.1089x over previous
#include <cuda_runtime.h>
#include <cuda_fp16.h>
#include <cstdint>

#define NN 50000
#define EE 800000
#define IN_CH 256
#define HEADS 4
#define OUT_CH 32
#define HC 128
#define NEG_SLOPE 0.2f
#define EPSV 1e-16f

#define SCAN_T 1024
#define NB1 ((NN + SCAN_T - 1) / SCAN_T)

#define BM 128
#define BN 128
#define BK 32
#define APAD 8   // halves; row = 40 halves = 80B (conflict-free fragment reads)

#define NGEMMB ((NN + BM - 1) / BM)          // 391
#define NDEGB  ((EE + 255) / 256)            // 3125

// ---------------- scratch ----------------
__device__ __half g_hh[(size_t)NN * HC];         // projected features, fp16
__device__ __half g_bh[HC * IN_CH];              // W as [n][k], fp16
__device__ float g_asrc[NN * HEADS];
__device__ float g_adst[NN * HEADS];
__device__ int   g_deg[NN];
__device__ int   g_offsets[NN + 1];
__device__ int   g_cursor[NN];
__device__ int   g_blocksums[NB1];
__device__ int   g_csr_src[EE];
__device__ float4 g_csr_w[EE];                   // unnormalized exp weights (CSR order)

// ---------------- 0: prep = zero degrees + W -> [n][k] fp16 table ----------------
__global__ void prep_kernel(const float* __restrict__ w) {
    int idx = blockIdx.x * blockDim.x + threadIdx.x;
    if (idx < NN) g_deg[idx] = 0;
    if (idx < HC * IN_CH) {
        int n = idx >> 8, k = idx & 255;
        g_bh[idx] = __float2half(w[(n >> 5) * (IN_CH * OUT_CH) + k * OUT_CH + (n & 31)]);
    }
}

// ---------------- 1: fp16 HMMA GEMM + fused attdot + fp16 h store + trailing deg ----------------
__global__ __launch_bounds__(256, 2) void gemm_mma_kernel(const float* __restrict__ x,
                                                          const float* __restrict__ att,
                                                          const int* __restrict__ ei) {
    if (blockIdx.x >= NGEMMB) {
        int e = (blockIdx.x - NGEMMB) * 256 + threadIdx.x;
        if (e < EE) atomicAdd(&g_deg[ei[EE + e]], 1);
        return;
    }

    __shared__ __half As[BM][BK + APAD];
    __shared__ __half Bs[BN][BK + APAD];
    __shared__ float s_a1[HEADS][OUT_CH];
    __shared__ float s_a2[HEADS][OUT_CH];
    const int tid = threadIdx.x;
    const int lane = tid & 31;
    const int wid = tid >> 5;
    const int wm = wid >> 1;
    const int wn = wid & 1;
    const int block_m = blockIdx.x * BM;
    const int g = lane >> 2;
    const int tg = lane & 3;

    if (tid < HEADS * OUT_CH) {
        int hh = tid >> 5, cc = tid & 31;
        s_a1[hh][cc] = att[hh * (2 * OUT_CH) + cc];
        s_a2[hh][cc] = att[hh * (2 * OUT_CH) + OUT_CH + cc];
    }

    float c[2][8][4];
#pragma unroll
    for (int mt = 0; mt < 2; mt++)
#pragma unroll
        for (int nt = 0; nt < 8; nt++)
#pragma unroll
            for (int j = 0; j < 4; j++) c[mt][nt][j] = 0.f;

    // loader geometry: 512 chunks of 8 halves per tile; 2 chunks/thread
    // idx = tid + i*256; r = idx>>2 (row 0..127), c8 = idx&3 (8-half group)
    // ---- initial tile 0 ----
    {
#pragma unroll
        for (int i = 0; i < 2; i++) {
            int idx = tid + i * 256;
            int r = idx >> 2, c8 = idx & 3;
            int gm = block_m + r;
            float4 v0 = make_float4(0.f, 0.f, 0.f, 0.f), v1 = v0;
            if (gm < NN) {
                v0 = *(const float4*)(x + (size_t)gm * IN_CH + c8 * 8);
                v1 = *(const float4*)(x + (size_t)gm * IN_CH + c8 * 8 + 4);
            }
            __half2 h0 = __floats2half2_rn(v0.x, v0.y);
            __half2 h1 = __floats2half2_rn(v0.z, v0.w);
            __half2 h2 = __floats2half2_rn(v1.x, v1.y);
            __half2 h3 = __floats2half2_rn(v1.z, v1.w);
            __half2* dst = (__half2*)&As[r][c8 * 8];
            dst[0] = h0; dst[1] = h1; dst[2] = h2; dst[3] = h3;
            // B tile: Bs[n][k] from g_bh[n*256 + k]
            *(uint4*)&Bs[r][c8 * 8] = *(const uint4*)(g_bh + r * IN_CH + c8 * 8);
        }
    }
    __syncthreads();

    for (int k0 = 0; k0 < IN_CH; k0 += BK) {
        const bool has_next = (k0 + BK) < IN_CH;
        float4 pa0[2], pa1[2];
        uint4 pbv[2];
        if (has_next) {
#pragma unroll
            for (int i = 0; i < 2; i++) {
                int idx = tid + i * 256;
                int r = idx >> 2, c8 = idx & 3;
                int gm = block_m + r;
                pa0[i] = make_float4(0.f, 0.f, 0.f, 0.f);
                pa1[i] = pa0[i];
                if (gm < NN) {
                    pa0[i] = *(const float4*)(x + (size_t)gm * IN_CH + k0 + BK + c8 * 8);
                    pa1[i] = *(const float4*)(x + (size_t)gm * IN_CH + k0 + BK + c8 * 8 + 4);
                }
                pbv[i] = *(const uint4*)(g_bh + r * IN_CH + k0 + BK + c8 * 8);
            }
        }

#pragma unroll
        for (int kk = 0; kk < BK; kk += 16) {
            uint32_t a[2][4];
#pragma unroll
            for (int mt = 0; mt < 2; mt++) {
                int ar = wm * 32 + mt * 16 + g;
                a[mt][0] = *(const uint32_t*)&As[ar][kk + 2 * tg];
                a[mt][1] = *(const uint32_t*)&As[ar + 8][kk + 2 * tg];
                a[mt][2] = *(const uint32_t*)&As[ar][kk + 2 * tg + 8];
                a[mt][3] = *(const uint32_t*)&As[ar + 8][kk + 2 * tg + 8];
            }
#pragma unroll
            for (int nt = 0; nt < 8; nt++) {
                int bc = wn * 64 + nt * 8 + g;
                uint32_t b0 = *(const uint32_t*)&Bs[bc][kk + 2 * tg];
                uint32_t b1 = *(const uint32_t*)&Bs[bc][kk + 2 * tg + 8];
#pragma unroll
                for (int mt = 0; mt < 2; mt++) {
                    asm volatile(
                        "mma.sync.aligned.m16n8k16.row.col.f32.f16.f16.f32 "
                        "{%0,%1,%2,%3}, {%4,%5,%6,%7}, {%8,%9}, {%0,%1,%2,%3};"
                        : "+f"(c[mt][nt][0]), "+f"(c[mt][nt][1]),
                          "+f"(c[mt][nt][2]), "+f"(c[mt][nt][3])
                        : "r"(a[mt][0]), "r"(a[mt][1]), "r"(a[mt][2]), "r"(a[mt][3]),
                          "r"(b0), "r"(b1));
                }
            }
        }
        __syncthreads();
        if (has_next) {
#pragma unroll
            for (int i = 0; i < 2; i++) {
                int idx = tid + i * 256;
                int r = idx >> 2, c8 = idx & 3;
                __half2 h0 = __floats2half2_rn(pa0[i].x, pa0[i].y);
                __half2 h1 = __floats2half2_rn(pa0[i].z, pa0[i].w);
                __half2 h2 = __floats2half2_rn(pa1[i].x, pa1[i].y);
                __half2 h3 = __floats2half2_rn(pa1[i].z, pa1[i].w);
                __half2* dst = (__half2*)&As[r][c8 * 8];
                dst[0] = h0; dst[1] = h1; dst[2] = h2; dst[3] = h3;
                *(uint4*)&Bs[r][c8 * 8] = pbv[i];
            }
            __syncthreads();
        }
    }

    // ---- epilogue: fp16 h store + fused attention dots (C layout unchanged) ----
    float ps[2][2][2], pd[2][2][2];
#pragma unroll
    for (int mt = 0; mt < 2; mt++)
#pragma unroll
        for (int rh = 0; rh < 2; rh++)
#pragma unroll
            for (int hl = 0; hl < 2; hl++) { ps[mt][rh][hl] = 0.f; pd[mt][rh][hl] = 0.f; }

#pragma unroll
    for (int mt = 0; mt < 2; mt++) {
#pragma unroll
        for (int nt = 0; nt < 8; nt++) {
            const int col = wn * 64 + nt * 8 + tg * 2;
            const int hl = nt >> 2;
            const int head = 2 * wn + hl;
            const int colh = (nt & 3) * 8 + tg * 2;
            const float a10 = s_a1[head][colh], a11 = s_a1[head][colh + 1];
            const float a20 = s_a2[head][colh], a21 = s_a2[head][colh + 1];
            const int r0 = block_m + wm * 32 + mt * 16 + g;
            const int r1 = r0 + 8;
            if (r0 < NN)
                *(__half2*)(g_hh + (size_t)r0 * HC + col) =
                    __floats2half2_rn(c[mt][nt][0], c[mt][nt][1]);
            if (r1 < NN)
                *(__half2*)(g_hh + (size_t)r1 * HC + col) =
                    __floats2half2_rn(c[mt][nt][2], c[mt][nt][3]);
            ps[mt][0][hl] += c[mt][nt][0] * a10 + c[mt][nt][1] * a11;
            ps[mt][1][hl] += c[mt][nt][2] * a10 + c[mt][nt][3] * a11;
            pd[mt][0][hl] += c[mt][nt][0] * a20 + c[mt][nt][1] * a21;
            pd[mt][1][hl] += c[mt][nt][2] * a20 + c[mt][nt][3] * a21;
        }
    }
#pragma unroll
    for (int off = 1; off <= 2; off <<= 1) {
#pragma unroll
        for (int mt = 0; mt < 2; mt++)
#pragma unroll
            for (int rh = 0; rh < 2; rh++)
#pragma unroll
                for (int hl = 0; hl < 2; hl++) {
                    ps[mt][rh][hl] += __shfl_xor_sync(0xFFFFFFFF, ps[mt][rh][hl], off);
                    pd[mt][rh][hl] += __shfl_xor_sync(0xFFFFFFFF, pd[mt][rh][hl], off);
                }
    }
    if (tg == 0) {
#pragma unroll
        for (int mt = 0; mt < 2; mt++)
#pragma unroll
            for (int rh = 0; rh < 2; rh++) {
                int row = block_m + wm * 32 + mt * 16 + g + rh * 8;
                if (row < NN) {
#pragma unroll
                    for (int hl = 0; hl < 2; hl++) {
                        g_asrc[row * 4 + 2 * wn + hl] = ps[mt][rh][hl];
                        g_adst[row * 4 + 2 * wn + hl] = pd[mt][rh][hl];
                    }
                }
            }
    }
}

// ---------------- 4a: scan degrees within tiles ----------------
__global__ void scan1_kernel() {
    __shared__ int sm[SCAN_T];
    int b = blockIdx.x, t = threadIdx.x;
    int i = b * SCAN_T + t;
    int v = (i < NN) ? g_deg[i] : 0;
    sm[t] = v;
    __syncthreads();
    for (int off = 1; off < SCAN_T; off <<= 1) {
        int add = (t >= off) ? sm[t - off] : 0;
        __syncthreads();
        sm[t] += add;
        __syncthreads();
    }
    if (i < NN) g_offsets[i] = sm[t] - v;
    if (t == SCAN_T - 1) g_blocksums[b] = sm[t];
}

// ---------------- 4b: add tile prefix (computed in-block) + init cursor ----------------
__global__ void scan3_kernel() {
    __shared__ int s_pref;
    int t = threadIdx.x;
    int base = blockIdx.x * 256;
    int tile = base >> 10;
    if (t < 32) {
        int acc = 0;
        for (int j = t; j < tile; j += 32) acc += g_blocksums[j];
#pragma unroll
        for (int off = 16; off > 0; off >>= 1)
            acc += __shfl_xor_sync(0xFFFFFFFF, acc, off);
        if (t == 0) s_pref = acc;
    }
    __syncthreads();
    int i = base + t;
    if (i < NN) {
        int o = g_offsets[i] + s_pref;
        g_offsets[i] = o;
        g_cursor[i] = o;
    }
    if (i == 0) g_offsets[NN] = EE;
}

// ---------------- 5: fused edge pass: exp(leakyrelu) -> CSR slot (sequential-write form) ----------------
__global__ void edgefill_kernel(const int* __restrict__ ei) {
    int e = blockIdx.x * blockDim.x + threadIdx.x;
    if (e >= EE) return;
    int src = ei[e];
    int dst = ei[EE + e];
    float4 as = *(const float4*)(g_asrc + src * 4);
    float4 ad = *(const float4*)(g_adst + dst * 4);
    float al0 = as.x + ad.x, al1 = as.y + ad.y, al2 = as.z + ad.z, al3 = as.w + ad.w;
    al0 = al0 > 0.f ? al0 : NEG_SLOPE * al0;
    al1 = al1 > 0.f ? al1 : NEG_SLOPE * al1;
    al2 = al2 > 0.f ? al2 : NEG_SLOPE * al2;
    al3 = al3 > 0.f ? al3 : NEG_SLOPE * al3;
    float4 ex = make_float4(__expf(al0), __expf(al1), __expf(al2), __expf(al3));
    int pos = atomicAdd(&g_cursor[dst], 1);
    g_csr_src[pos] = src;
    g_csr_w[pos] = ex;
}

// ---------------- 6: gather-aggregate, fp16 h, sequential weight reads ----------------
__global__ __launch_bounds__(128) void aggregate_kernel(float* __restrict__ out,
                                                        const float* __restrict__ bias) {
    int n = blockIdx.x;
    int t = threadIdx.x;
    int head = t >> 5;
    int beg = g_offsets[n];
    int end = g_offsets[n + 1];
    const float* wbase = (const float*)g_csr_w;
    const __half* hb = g_hh + t;
    float acc = 0.f, sw = 0.f;
    int i = beg;
    for (; i + 3 < end; i += 4) {
        int s0 = g_csr_src[i];
        int s1 = g_csr_src[i + 1];
        int s2 = g_csr_src[i + 2];
        int s3 = g_csr_src[i + 3];
        float w0 = wbase[(size_t)i * 4 + head];
        float w1 = wbase[(size_t)(i + 1) * 4 + head];
        float w2 = wbase[(size_t)(i + 2) * 4 + head];
        float w3 = wbase[(size_t)(i + 3) * 4 + head];
        float v0 = __half2float(hb[(size_t)s0 * HC]);
        float v1 = __half2float(hb[(size_t)s1 * HC]);
        float v2 = __half2float(hb[(size_t)s2 * HC]);
        float v3 = __half2float(hb[(size_t)s3 * HC]);
        acc += v0 * w0 + v1 * w1 + v2 * w2 + v3 * w3;
        sw += w0 + w1 + w2 + w3;
    }
    for (; i < end; i++) {
        int s0 = g_csr_src[i];
        float w0 = wbase[(size_t)i * 4 + head];
        acc += __half2float(hb[(size_t)s0 * HC]) * w0;
        sw += w0;
    }
    out[(size_t)n * HC + t] = acc / (sw + EPSV) + __ldg(bias + t);
}

// ---------------- launcher ----------------
extern "C" void kernel_launch(void* const* d_in, const int* in_sizes, int n_in,
                              void* d_out, int out_size) {
    const float* x    = (const float*)d_in[0];
    const int* ei     = (const int*)d_in[1];
    const float* w    = (const float*)d_in[2];
    const float* att  = (const float*)d_in[3];
    const float* bias = (const float*)d_in[4];
    float* out = (float*)d_out;

    prep_kernel<<<(NN + 255) / 256, 256>>>(w);
    gemm_mma_kernel<<<NGEMMB + NDEGB, 256>>>(x, att, ei);
    scan1_kernel<<<NB1, SCAN_T>>>();
    scan3_kernel<<<(NN + 255) / 256, 256>>>();
    edgefill_kernel<<<(EE + 255) / 256, 256>>>(ei);
    aggregate_kernel<<<NN, 128>>>(out, bias);
}